// round 3
// baseline (speedup 1.0000x reference)
#include <cuda_runtime.h>
#include <math.h>

#define BB 2
#define SS 2048
#define DD 1024
#define HH 16
#define DH 64
#define MTOT (BB*SS)   // 4096

// Scratch (allocation-free rule: __device__ globals)
__device__ float g_Q[MTOT*DD];
__device__ float g_K[MTOT*DD];
__device__ float g_V[MTOT*DD];
__device__ float g_O[MTOT*DD];

// ---------------------------------------------------------------------------
// GEMM: C[M,N] = A[M,K] @ W[N,K]^T + bias[N]   (torch Linear, NT layout)
// 128x128 tile, BK=8, 256 threads, 8x8 micro-tile.
// ---------------------------------------------------------------------------
__global__ __launch_bounds__(256) void gemm_nt_bias(
    const float* __restrict__ A, const float* __restrict__ W,
    const float* __restrict__ bias, float* __restrict__ C,
    int M, int N, int K)
{
    __shared__ float As[8][128];
    __shared__ float Ws[8][128];

    const int tid = threadIdx.x;
    const int bm = blockIdx.y * 128;
    const int bn = blockIdx.x * 128;

    const int lrow = tid >> 1;          // 0..127
    const int lcol = (tid & 1) * 4;     // 0 or 4

    const int tm = (tid >> 4) << 3;     // 0..120
    const int tn = (tid & 15) << 3;     // 0..120

    float acc[8][8];
    #pragma unroll
    for (int i = 0; i < 8; i++)
        #pragma unroll
        for (int j = 0; j < 8; j++) acc[i][j] = 0.0f;

    const float* Ap = A + (size_t)(bm + lrow) * K + lcol;
    const float* Wp = W + (size_t)(bn + lrow) * K + lcol;

    for (int k0 = 0; k0 < K; k0 += 8) {
        float4 a4 = *(const float4*)(Ap + k0);
        float4 w4 = *(const float4*)(Wp + k0);

        __syncthreads();
        As[lcol + 0][lrow] = a4.x;
        As[lcol + 1][lrow] = a4.y;
        As[lcol + 2][lrow] = a4.z;
        As[lcol + 3][lrow] = a4.w;
        Ws[lcol + 0][lrow] = w4.x;
        Ws[lcol + 1][lrow] = w4.y;
        Ws[lcol + 2][lrow] = w4.z;
        Ws[lcol + 3][lrow] = w4.w;
        __syncthreads();

        #pragma unroll
        for (int k = 0; k < 8; k++) {
            float4 a0 = *(const float4*)&As[k][tm];
            float4 a1 = *(const float4*)&As[k][tm + 4];
            float4 b0 = *(const float4*)&Ws[k][tn];
            float4 b1 = *(const float4*)&Ws[k][tn + 4];
            float ar[8] = {a0.x, a0.y, a0.z, a0.w, a1.x, a1.y, a1.z, a1.w};
            float br[8] = {b0.x, b0.y, b0.z, b0.w, b1.x, b1.y, b1.z, b1.w};
            #pragma unroll
            for (int i = 0; i < 8; i++)
                #pragma unroll
                for (int j = 0; j < 8; j++)
                    acc[i][j] = fmaf(ar[i], br[j], acc[i][j]);
        }
    }

    #pragma unroll
    for (int i = 0; i < 8; i++) {
        float* Cp = C + (size_t)(bm + tm + i) * N + bn + tn;
        const float* bp = bias + bn + tn;
        float4 c0, c1;
        c0.x = acc[i][0] + bp[0]; c0.y = acc[i][1] + bp[1];
        c0.z = acc[i][2] + bp[2]; c0.w = acc[i][3] + bp[3];
        c1.x = acc[i][4] + bp[4]; c1.y = acc[i][5] + bp[5];
        c1.z = acc[i][6] + bp[6]; c1.w = acc[i][7] + bp[7];
        *(float4*)(Cp + 0) = c0;
        *(float4*)(Cp + 4) = c1;
    }
}

// ---------------------------------------------------------------------------
// Flash attention, fp32. One thread owns one query row (q regs + O accum in
// registers), block = 128 threads = 128 query rows of one (b,h).
// K/V tiles of 32 rows staged in smem; online softmax.
// ---------------------------------------------------------------------------
#define KT 32

__global__ __launch_bounds__(128) void flash_attn_kernel()
{
    __shared__ float Ks[KT][DH];
    __shared__ float Vs[KT][DH];

    const int b = blockIdx.z;
    const int h = blockIdx.y;
    const int q = blockIdx.x * 128 + threadIdx.x;

    const float* Qp = g_Q + (size_t)(b * SS + q) * DD + h * DH;

    float qr[DH];
    #pragma unroll
    for (int d = 0; d < DH; d += 4) {
        float4 t = *(const float4*)(Qp + d);
        qr[d] = t.x; qr[d+1] = t.y; qr[d+2] = t.z; qr[d+3] = t.w;
    }

    float o[DH];
    #pragma unroll
    for (int d = 0; d < DH; d++) o[d] = 0.0f;

    float m = -1e30f;
    float l = 0.0f;

    for (int kt = 0; kt < SS; kt += KT) {
        const float* Kp = g_K + (size_t)(b * SS + kt) * DD + h * DH;
        const float* Vp = g_V + (size_t)(b * SS + kt) * DD + h * DH;

        // cooperative tile load: KT*DH/4 = 512 float4 per tile, 128 threads
        #pragma unroll
        for (int i = threadIdx.x; i < KT * (DH / 4); i += 128) {
            int r = i / (DH / 4);
            int c = (i % (DH / 4)) * 4;
            *(float4*)&Ks[r][c] = *(const float4*)(Kp + (size_t)r * DD + c);
            *(float4*)&Vs[r][c] = *(const float4*)(Vp + (size_t)r * DD + c);
        }
        __syncthreads();

        // scores for this tile
        float s[KT];
        #pragma unroll
        for (int j = 0; j < KT; j++) {
            float acc = 0.0f;
            #pragma unroll
            for (int d = 0; d < DH; d += 4) {
                float4 k4 = *(const float4*)&Ks[j][d];
                acc = fmaf(qr[d],   k4.x, acc);
                acc = fmaf(qr[d+1], k4.y, acc);
                acc = fmaf(qr[d+2], k4.z, acc);
                acc = fmaf(qr[d+3], k4.w, acc);
            }
            s[j] = acc * 0.125f;   // 1/sqrt(64)
        }

        // online softmax update
        float mt = m;
        #pragma unroll
        for (int j = 0; j < KT; j++) mt = fmaxf(mt, s[j]);
        float scale = __expf(m - mt);
        #pragma unroll
        for (int d = 0; d < DH; d++) o[d] *= scale;

        float lsum = 0.0f;
        #pragma unroll
        for (int j = 0; j < KT; j++) {
            float p = __expf(s[j] - mt);
            lsum += p;
            #pragma unroll
            for (int d = 0; d < DH; d += 4) {
                float4 v4 = *(const float4*)&Vs[j][d];
                o[d]   = fmaf(p, v4.x, o[d]);
                o[d+1] = fmaf(p, v4.y, o[d+1]);
                o[d+2] = fmaf(p, v4.z, o[d+2]);
                o[d+3] = fmaf(p, v4.w, o[d+3]);
            }
        }
        l = l * scale + lsum;
        m = mt;
        __syncthreads();
    }

    const float inv = 1.0f / l;
    float* Op = g_O + (size_t)(b * SS + q) * DD + h * DH;
    #pragma unroll
    for (int d = 0; d < DH; d += 4) {
        float4 t;
        t.x = o[d] * inv; t.y = o[d+1] * inv;
        t.z = o[d+2] * inv; t.w = o[d+3] * inv;
        *(float4*)(Op + d) = t;
    }
}

// ---------------------------------------------------------------------------
// Launch
// ---------------------------------------------------------------------------
extern "C" void kernel_launch(void* const* d_in, const int* in_sizes, int n_in,
                              void* d_out, int out_size)
{
    const float* x  = (const float*)d_in[0];
    const float* Wq = (const float*)d_in[1];
    const float* bq = (const float*)d_in[2];
    const float* Wk = (const float*)d_in[3];
    const float* bk = (const float*)d_in[4];
    const float* Wv = (const float*)d_in[5];
    const float* bv = (const float*)d_in[6];
    const float* Wo = (const float*)d_in[7];
    const float* bo = (const float*)d_in[8];
    float* out = (float*)d_out;

    float *Q, *K, *V, *O;
    cudaGetSymbolAddress((void**)&Q, g_Q);
    cudaGetSymbolAddress((void**)&K, g_K);
    cudaGetSymbolAddress((void**)&V, g_V);
    cudaGetSymbolAddress((void**)&O, g_O);

    dim3 gemm_grid(DD / 128, MTOT / 128);   // (8, 32)
    gemm_nt_bias<<<gemm_grid, 256>>>(x, Wq, bq, Q, MTOT, DD, DD);
    gemm_nt_bias<<<gemm_grid, 256>>>(x, Wk, bk, K, MTOT, DD, DD);
    gemm_nt_bias<<<gemm_grid, 256>>>(x, Wv, bv, V, MTOT, DD, DD);

    dim3 fa_grid(SS / 128, HH, BB);         // (16, 16, 2)
    flash_attn_kernel<<<fa_grid, 128>>>();

    gemm_nt_bias<<<gemm_grid, 256>>>(O, Wo, bo, out, MTOT, DD, DD);
}

// round 5
// speedup vs baseline: 2.7037x; 2.7037x over previous
#include <cuda_runtime.h>
#include <cuda_bf16.h>
#include <math.h>
#include <stdint.h>

#define BB 2
#define SS 2048
#define DD 1024
#define HH 16
#define DH 64
#define MTOT (BB*SS)   // 4096

// ---------------------------------------------------------------------------
// Scratch (allocation-free rule: __device__ globals)
// ---------------------------------------------------------------------------
__device__ __nv_bfloat16 g_xhi[MTOT*DD], g_xlo[MTOT*DD];
__device__ __nv_bfloat16 g_qhi[MTOT*DD], g_qlo[MTOT*DD];
__device__ __nv_bfloat16 g_khi[MTOT*DD], g_klo[MTOT*DD];
__device__ __nv_bfloat16 g_vhi[MTOT*DD], g_vlo[MTOT*DD];
__device__ __nv_bfloat16 g_ohi[MTOT*DD], g_olo[MTOT*DD];
__device__ __nv_bfloat16 g_whi[4][DD*DD], g_wlo[4][DD*DD];

// ---------------------------------------------------------------------------
// Helpers (baseline ISA only: mma.sync / cp.async — no tcgen05, no clusters)
// ---------------------------------------------------------------------------
__device__ __forceinline__ uint32_t smem_u32(const void* p) {
    uint32_t r;
    asm("{ .reg .u64 t; cvta.to.shared.u64 t, %1; cvt.u32.u64 %0, t; }"
        : "=r"(r) : "l"(p));
    return r;
}
__device__ __forceinline__ void cp16(uint32_t dst, const void* src) {
    asm volatile("cp.async.cg.shared.global [%0], [%1], 16;" :: "r"(dst), "l"(src));
}
__device__ __forceinline__ void cp_commit() { asm volatile("cp.async.commit_group;"); }
__device__ __forceinline__ void cp_wait0()  { asm volatile("cp.async.wait_group 0;" ::: "memory"); }

__device__ __forceinline__ uint32_t lds32(uint32_t a) {
    uint32_t v; asm volatile("ld.shared.b32 %0, [%1];" : "=r"(v) : "r"(a)); return v;
}
__device__ __forceinline__ void sts32(uint32_t a, uint32_t v) {
    asm volatile("st.shared.b32 [%0], %1;" :: "r"(a), "r"(v));
}

__device__ __forceinline__ void mma16816(float* d,
    uint32_t a0, uint32_t a1, uint32_t a2, uint32_t a3, uint32_t b0, uint32_t b1) {
    asm volatile(
        "mma.sync.aligned.m16n8k16.row.col.f32.bf16.bf16.f32 "
        "{%0,%1,%2,%3}, {%4,%5,%6,%7}, {%8,%9}, {%0,%1,%2,%3};"
        : "+f"(d[0]), "+f"(d[1]), "+f"(d[2]), "+f"(d[3])
        : "r"(a0), "r"(a1), "r"(a2), "r"(a3), "r"(b0), "r"(b1));
}

// pack (lo, hi) floats -> bf16x2 in one reg (lo in bits [0:16))
__device__ __forceinline__ uint32_t packbf(float lo, float hi) {
    __nv_bfloat162 t = __floats2bfloat162_rn(lo, hi);   // .x = lo half
    return *(uint32_t*)&t;
}
__device__ __forceinline__ float fast_exp2(float x) {
    float y; asm("ex2.approx.ftz.f32 %0, %1;" : "=f"(y) : "f"(x)); return y;
}

// ---------------------------------------------------------------------------
// fp32 -> bf16 (hi, lo) split kernel. 4 elements / thread.
// ---------------------------------------------------------------------------
__global__ __launch_bounds__(256) void split_fp32_bf16(
    const float* __restrict__ in, __nv_bfloat16* __restrict__ hi,
    __nv_bfloat16* __restrict__ lo, int n4)
{
    int i = blockIdx.x * 256 + threadIdx.x;
    if (i >= n4) return;
    float4 v = *(const float4*)(in + (size_t)i * 4);
    __nv_bfloat16 h0 = __float2bfloat16(v.x);
    __nv_bfloat16 h1 = __float2bfloat16(v.y);
    __nv_bfloat16 h2 = __float2bfloat16(v.z);
    __nv_bfloat16 h3 = __float2bfloat16(v.w);
    __nv_bfloat16 l0 = __float2bfloat16(v.x - __bfloat162float(h0));
    __nv_bfloat16 l1 = __float2bfloat16(v.y - __bfloat162float(h1));
    __nv_bfloat16 l2 = __float2bfloat16(v.z - __bfloat162float(h2));
    __nv_bfloat16 l3 = __float2bfloat16(v.w - __bfloat162float(h3));
    __nv_bfloat162* hp = (__nv_bfloat162*)(hi + (size_t)i * 4);
    __nv_bfloat162* lp = (__nv_bfloat162*)(lo + (size_t)i * 4);
    hp[0] = __nv_bfloat162{h0, h1}; hp[1] = __nv_bfloat162{h2, h3};
    lp[0] = __nv_bfloat162{l0, l1}; lp[1] = __nv_bfloat162{l2, l3};
}

// ---------------------------------------------------------------------------
// mma.sync bf16 3-split GEMM:  C[M,N] = (Ahi+Alo)[M,K] @ (Bhi+Blo)[N,K]^T + bias
// 128x128 tile, BK=32, 256 threads (8 warps, 4m x 2n), warp tile 32x64.
// Smem rows padded to 80B -> conflict-free frag loads. cp.async double buffer.
// mode 0: write float C.  mode 1: write split bf16 (Chi, Clo).
// ---------------------------------------------------------------------------
#define G_TILE 10240            // 128 rows * 80B
#define G_STAGE (4*G_TILE)      // Ahi, Alo, Bhi, Blo
#define G_SMEM (2*G_STAGE)      // 81920

__global__ __launch_bounds__(256) void gemm_mma(
    const __nv_bfloat16* __restrict__ Ahi, const __nv_bfloat16* __restrict__ Alo,
    const __nv_bfloat16* __restrict__ Bhi, const __nv_bfloat16* __restrict__ Blo,
    const float* __restrict__ bias,
    float* __restrict__ Cf,
    __nv_bfloat16* __restrict__ Chi, __nv_bfloat16* __restrict__ Clo,
    int mode)
{
    extern __shared__ char smem[];
    const uint32_t sb = smem_u32(smem);
    const int tid = threadIdx.x, lane = tid & 31, wid = tid >> 5;
    const int g = lane >> 2, qr = lane & 3;
    const int bm = blockIdx.y * 128, bn = blockIdx.x * 128;
    const int wm = (wid >> 1) * 32, wn = (wid & 1) * 64;

    float acc[2][8][4];
    #pragma unroll
    for (int i = 0; i < 2; i++)
        #pragma unroll
        for (int j = 0; j < 8; j++)
            #pragma unroll
            for (int k = 0; k < 4; k++) acc[i][j][k] = 0.0f;

    const int lrow = tid >> 2, lseg = tid & 3;

    auto load_stage = [&](int c) {
        uint32_t base = sb + (uint32_t)(c & 1) * G_STAGE;
        #pragma unroll
        for (int t = 0; t < 4; t++) {
            const __nv_bfloat16* gp = (t == 0 ? Ahi : t == 1 ? Alo : t == 2 ? Bhi : Blo);
            int rb = (t < 2 ? bm : bn);
            #pragma unroll
            for (int h2 = 0; h2 < 2; h2++) {
                int row = h2 * 64 + lrow;
                cp16(base + t * G_TILE + row * 80 + lseg * 16,
                     (const char*)(gp + (size_t)(rb + row) * DD + c * 32) + lseg * 16);
            }
        }
        cp_commit();
    };

    load_stage(0);

    for (int c = 0; c < 32; c++) {
        cp_wait0();
        __syncthreads();
        if (c < 31) load_stage(c + 1);

        uint32_t base = sb + (uint32_t)(c & 1) * G_STAGE;
        #pragma unroll
        for (int kc = 0; kc < 2; kc++) {
            uint32_t ah[2][4], al[2][4];
            #pragma unroll
            for (int mf = 0; mf < 2; mf++) {
                uint32_t ra = base + (wm + mf * 16 + g) * 80 + kc * 32 + qr * 4;
                ah[mf][0] = lds32(ra);       ah[mf][1] = lds32(ra + 640);
                ah[mf][2] = lds32(ra + 16);  ah[mf][3] = lds32(ra + 656);
                uint32_t rl = ra + G_TILE;
                al[mf][0] = lds32(rl);       al[mf][1] = lds32(rl + 640);
                al[mf][2] = lds32(rl + 16);  al[mf][3] = lds32(rl + 656);
            }
            #pragma unroll
            for (int nb = 0; nb < 8; nb++) {
                uint32_t rb0 = base + 2 * G_TILE + (wn + nb * 8 + g) * 80 + kc * 32 + qr * 4;
                uint32_t bh0 = lds32(rb0), bh1 = lds32(rb0 + 16);
                uint32_t rbl = rb0 + G_TILE;
                uint32_t bl0 = lds32(rbl), bl1 = lds32(rbl + 16);
                #pragma unroll
                for (int mf = 0; mf < 2; mf++) {
                    mma16816(acc[mf][nb], ah[mf][0], ah[mf][1], ah[mf][2], ah[mf][3], bh0, bh1);
                    mma16816(acc[mf][nb], ah[mf][0], ah[mf][1], ah[mf][2], ah[mf][3], bl0, bl1);
                    mma16816(acc[mf][nb], al[mf][0], al[mf][1], al[mf][2], al[mf][3], bh0, bh1);
                }
            }
        }
    }

    // epilogue
    #pragma unroll
    for (int mf = 0; mf < 2; mf++) {
        #pragma unroll
        for (int nb = 0; nb < 8; nb++) {
            int col = bn + wn + nb * 8 + qr * 2;
            float b0 = bias[col], b1 = bias[col + 1];
            int r0 = bm + wm + mf * 16 + g;
            float v00 = acc[mf][nb][0] + b0, v01 = acc[mf][nb][1] + b1;
            float v10 = acc[mf][nb][2] + b0, v11 = acc[mf][nb][3] + b1;
            if (mode == 0) {
                *(float2*)(Cf + (size_t)r0 * DD + col) = make_float2(v00, v01);
                *(float2*)(Cf + (size_t)(r0 + 8) * DD + col) = make_float2(v10, v11);
            } else {
                __nv_bfloat16 h00 = __float2bfloat16(v00), h01 = __float2bfloat16(v01);
                __nv_bfloat16 h10 = __float2bfloat16(v10), h11 = __float2bfloat16(v11);
                __nv_bfloat16 e00 = __float2bfloat16(v00 - __bfloat162float(h00));
                __nv_bfloat16 e01 = __float2bfloat16(v01 - __bfloat162float(h01));
                __nv_bfloat16 e10 = __float2bfloat16(v10 - __bfloat162float(h10));
                __nv_bfloat16 e11 = __float2bfloat16(v11 - __bfloat162float(h11));
                *(__nv_bfloat162*)(Chi + (size_t)r0 * DD + col)       = __nv_bfloat162{h00, h01};
                *(__nv_bfloat162*)(Chi + (size_t)(r0 + 8) * DD + col) = __nv_bfloat162{h10, h11};
                *(__nv_bfloat162*)(Clo + (size_t)r0 * DD + col)       = __nv_bfloat162{e00, e01};
                *(__nv_bfloat162*)(Clo + (size_t)(r0 + 8) * DD + col) = __nv_bfloat162{e10, e11};
            }
        }
    }
}

// ---------------------------------------------------------------------------
// Flash attention on mma.sync bf16.
// CTA: 128 threads (4 warps), 64 query rows (16/warp). Key tiles of 64.
// S = Qhi·Khi + Qhi·Klo + Qlo·Khi (3-split, fp32 accum); P bf16;
// O += P·Vhi + P·Vlo (V transposed in smem so B-frags are single LDS.32).
// Smem rows padded to 144B -> conflict-free. Writes split-bf16 O.
// ---------------------------------------------------------------------------
#define F_TILE 9216             // 64 rows * 144B
#define F_STAGE (4*F_TILE)      // Khi, Klo, Vthi, Vtlo
#define F_SMEM (2*F_STAGE)      // 73728
#define EXC 0.18033688011112042f   // 0.125 * log2(e)

__global__ __launch_bounds__(128) void flash_mma(
    const __nv_bfloat16* __restrict__ qhi, const __nv_bfloat16* __restrict__ qlo,
    const __nv_bfloat16* __restrict__ khi, const __nv_bfloat16* __restrict__ klo,
    const __nv_bfloat16* __restrict__ vhi, const __nv_bfloat16* __restrict__ vlo,
    __nv_bfloat16* __restrict__ ohi, __nv_bfloat16* __restrict__ olo)
{
    extern __shared__ char smem[];
    const uint32_t sb = smem_u32(smem);
    const int tid = threadIdx.x, lane = tid & 31, w = tid >> 5;
    const int g = lane >> 2, qr = lane & 3;
    const int b = blockIdx.z, h = blockIdx.y;
    const int q0 = blockIdx.x * 64;

    // Q fragments (held for the whole kernel)
    uint32_t qh_[4][4], ql_[4][4];
    {
        const size_t rowb = (size_t)(b * SS + q0 + w * 16 + g) * DD + h * DH;
        #pragma unroll
        for (int kc = 0; kc < 4; kc++) {
            size_t o0 = rowb + kc * 16 + qr * 2;
            qh_[kc][0] = *(const uint32_t*)(qhi + o0);
            qh_[kc][1] = *(const uint32_t*)(qhi + o0 + 8 * DD);
            qh_[kc][2] = *(const uint32_t*)(qhi + o0 + 8);
            qh_[kc][3] = *(const uint32_t*)(qhi + o0 + 8 * DD + 8);
            ql_[kc][0] = *(const uint32_t*)(qlo + o0);
            ql_[kc][1] = *(const uint32_t*)(qlo + o0 + 8 * DD);
            ql_[kc][2] = *(const uint32_t*)(qlo + o0 + 8);
            ql_[kc][3] = *(const uint32_t*)(qlo + o0 + 8 * DD + 8);
        }
    }

    float o_[8][4];
    #pragma unroll
    for (int j = 0; j < 8; j++)
        #pragma unroll
        for (int k = 0; k < 4; k++) o_[j][k] = 0.0f;
    float m0 = -1e30f, m1 = -1e30f, l0 = 0.0f, l1 = 0.0f;

    auto load_tiles = [&](int t) {
        uint32_t base = sb + (uint32_t)(t & 1) * F_STAGE;
        // K tiles via cp.async (natural [key][dh] layout)
        #pragma unroll
        for (int s2 = 0; s2 < 2; s2++) {
            const __nv_bfloat16* kp = s2 ? klo : khi;
            #pragma unroll
            for (int i = 0; i < 4; i++) {
                int flat = i * 128 + tid;           // 0..511
                int row = flat >> 3, seg = flat & 7;
                cp16(base + s2 * F_TILE + row * 144 + seg * 16,
                     (const char*)(kp + (size_t)(b * SS + t * 64 + row) * DD + h * DH) + seg * 16);
            }
        }
        cp_commit();
        // V tiles: transpose to [dh][key] via LDG.32 pairs -> STS.32
        #pragma unroll
        for (int i = 0; i < 16; i++) {
            int flat = i * 128 + tid;               // 0..2047
            int s2 = flat >> 10;
            int u = flat & 1023;
            int kp2 = u >> 5, dp = u & 31;
            const __nv_bfloat16* vp = (s2 ? vlo : vhi)
                + (size_t)(b * SS + t * 64 + kp2 * 2) * DD + h * DH + dp * 2;
            uint32_t w0 = *(const uint32_t*)vp;        // V[2kp][2dp..2dp+1]
            uint32_t w1 = *(const uint32_t*)(vp + DD); // V[2kp+1][...]
            uint32_t r0 = (w0 & 0xFFFFu) | (w1 << 16);          // Vt[2dp][2kp..2kp+1]
            uint32_t r1 = (w0 >> 16) | (w1 & 0xFFFF0000u);      // Vt[2dp+1][...]
            uint32_t vb = base + (2 + s2) * F_TILE;
            sts32(vb + (dp * 2) * 144 + kp2 * 4, r0);
            sts32(vb + (dp * 2 + 1) * 144 + kp2 * 4, r1);
        }
    };

    load_tiles(0);

    for (int t = 0; t < 32; t++) {
        cp_wait0();
        __syncthreads();
        if (t < 31) load_tiles(t + 1);
        uint32_t base = sb + (uint32_t)(t & 1) * F_STAGE;

        // ---- S = Q K^T (3-split) ----
        float s_[8][4];
        #pragma unroll
        for (int j = 0; j < 8; j++)
            #pragma unroll
            for (int k = 0; k < 4; k++) s_[j][k] = 0.0f;

        #pragma unroll
        for (int kc = 0; kc < 4; kc++) {
            #pragma unroll
            for (int nb = 0; nb < 8; nb++) {
                uint32_t rk = base + (nb * 8 + g) * 144 + kc * 32 + qr * 4;
                uint32_t kh0 = lds32(rk), kh1 = lds32(rk + 16);
                uint32_t kl0 = lds32(rk + F_TILE), kl1 = lds32(rk + F_TILE + 16);
                mma16816(s_[nb], qh_[kc][0], qh_[kc][1], qh_[kc][2], qh_[kc][3], kh0, kh1);
                mma16816(s_[nb], qh_[kc][0], qh_[kc][1], qh_[kc][2], qh_[kc][3], kl0, kl1);
                mma16816(s_[nb], ql_[kc][0], ql_[kc][1], ql_[kc][2], ql_[kc][3], kh0, kh1);
            }
        }

        // ---- online softmax ----
        float tm0 = -1e30f, tm1 = -1e30f;
        #pragma unroll
        for (int nb = 0; nb < 8; nb++) {
            tm0 = fmaxf(tm0, fmaxf(s_[nb][0], s_[nb][1]));
            tm1 = fmaxf(tm1, fmaxf(s_[nb][2], s_[nb][3]));
        }
        tm0 = fmaxf(tm0, __shfl_xor_sync(0xffffffffu, tm0, 1));
        tm0 = fmaxf(tm0, __shfl_xor_sync(0xffffffffu, tm0, 2));
        tm1 = fmaxf(tm1, __shfl_xor_sync(0xffffffffu, tm1, 1));
        tm1 = fmaxf(tm1, __shfl_xor_sync(0xffffffffu, tm1, 2));

        float mn0 = fmaxf(m0, tm0), mn1 = fmaxf(m1, tm1);
        float sc0 = fast_exp2((m0 - mn0) * EXC), sc1 = fast_exp2((m1 - mn1) * EXC);
        m0 = mn0; m1 = mn1;
        l0 *= sc0; l1 *= sc1;
        #pragma unroll
        for (int nb = 0; nb < 8; nb++) {
            o_[nb][0] *= sc0; o_[nb][1] *= sc0;
            o_[nb][2] *= sc1; o_[nb][3] *= sc1;
        }

        uint32_t pa[8][2];
        float ps0 = 0.0f, ps1 = 0.0f;
        #pragma unroll
        for (int nb = 0; nb < 8; nb++) {
            float p0 = fast_exp2((s_[nb][0] - m0) * EXC);
            float p1 = fast_exp2((s_[nb][1] - m0) * EXC);
            float p2 = fast_exp2((s_[nb][2] - m1) * EXC);
            float p3 = fast_exp2((s_[nb][3] - m1) * EXC);
            ps0 += p0 + p1; ps1 += p2 + p3;
            pa[nb][0] = packbf(p0, p1);
            pa[nb][1] = packbf(p2, p3);
        }
        ps0 += __shfl_xor_sync(0xffffffffu, ps0, 1);
        ps0 += __shfl_xor_sync(0xffffffffu, ps0, 2);
        ps1 += __shfl_xor_sync(0xffffffffu, ps1, 1);
        ps1 += __shfl_xor_sync(0xffffffffu, ps1, 2);
        l0 += ps0; l1 += ps1;

        // ---- O += P V (2-split on V) ----
        #pragma unroll
        for (int kc = 0; kc < 4; kc++) {
            uint32_t a0 = pa[2 * kc][0], a1 = pa[2 * kc][1];
            uint32_t a2 = pa[2 * kc + 1][0], a3 = pa[2 * kc + 1][1];
            #pragma unroll
            for (int nb = 0; nb < 8; nb++) {
                uint32_t rv = base + 2 * F_TILE + (nb * 8 + g) * 144 + kc * 32 + qr * 4;
                uint32_t vh0 = lds32(rv), vh1 = lds32(rv + 16);
                uint32_t vl0 = lds32(rv + F_TILE), vl1 = lds32(rv + F_TILE + 16);
                mma16816(o_[nb], a0, a1, a2, a3, vh0, vh1);
                mma16816(o_[nb], a0, a1, a2, a3, vl0, vl1);
            }
        }
    }

    // ---- epilogue: normalize, split to bf16 hi/lo ----
    float i0 = 1.0f / l0, i1 = 1.0f / l1;
    const size_t rw0 = (size_t)(b * SS + q0 + w * 16 + g) * DD + h * DH;
    #pragma unroll
    for (int nb = 0; nb < 8; nb++) {
        int col = nb * 8 + qr * 2;
        float v00 = o_[nb][0] * i0, v01 = o_[nb][1] * i0;
        float v10 = o_[nb][2] * i1, v11 = o_[nb][3] * i1;
        __nv_bfloat16 h00 = __float2bfloat16(v00), h01 = __float2bfloat16(v01);
        __nv_bfloat16 h10 = __float2bfloat16(v10), h11 = __float2bfloat16(v11);
        __nv_bfloat16 e00 = __float2bfloat16(v00 - __bfloat162float(h00));
        __nv_bfloat16 e01 = __float2bfloat16(v01 - __bfloat162float(h01));
        __nv_bfloat16 e10 = __float2bfloat16(v10 - __bfloat162float(h10));
        __nv_bfloat16 e11 = __float2bfloat16(v11 - __bfloat162float(h11));
        *(__nv_bfloat162*)(ohi + rw0 + col)          = __nv_bfloat162{h00, h01};
        *(__nv_bfloat162*)(ohi + rw0 + 8 * DD + col) = __nv_bfloat162{h10, h11};
        *(__nv_bfloat162*)(olo + rw0 + col)          = __nv_bfloat162{e00, e01};
        *(__nv_bfloat162*)(olo + rw0 + 8 * DD + col) = __nv_bfloat162{e10, e11};
    }
}

// ---------------------------------------------------------------------------
// Launch
// ---------------------------------------------------------------------------
extern "C" void kernel_launch(void* const* d_in, const int* in_sizes, int n_in,
                              void* d_out, int out_size)
{
    const float* x  = (const float*)d_in[0];
    const float* Wq = (const float*)d_in[1];
    const float* bq = (const float*)d_in[2];
    const float* Wk = (const float*)d_in[3];
    const float* bk = (const float*)d_in[4];
    const float* Wv = (const float*)d_in[5];
    const float* bv = (const float*)d_in[6];
    const float* Wo = (const float*)d_in[7];
    const float* bo = (const float*)d_in[8];
    float* out = (float*)d_out;

    __nv_bfloat16 *xhi, *xlo, *qhi, *qlo, *khi, *klo, *vhi, *vlo, *ohi, *olo, *whi, *wlo;
    cudaGetSymbolAddress((void**)&xhi, g_xhi); cudaGetSymbolAddress((void**)&xlo, g_xlo);
    cudaGetSymbolAddress((void**)&qhi, g_qhi); cudaGetSymbolAddress((void**)&qlo, g_qlo);
    cudaGetSymbolAddress((void**)&khi, g_khi); cudaGetSymbolAddress((void**)&klo, g_klo);
    cudaGetSymbolAddress((void**)&vhi, g_vhi); cudaGetSymbolAddress((void**)&vlo, g_vlo);
    cudaGetSymbolAddress((void**)&ohi, g_ohi); cudaGetSymbolAddress((void**)&olo, g_olo);
    cudaGetSymbolAddress((void**)&whi, g_whi); cudaGetSymbolAddress((void**)&wlo, g_wlo);

    cudaFuncSetAttribute(gemm_mma,  cudaFuncAttributeMaxDynamicSharedMemorySize, G_SMEM);
    cudaFuncSetAttribute(flash_mma, cudaFuncAttributeMaxDynamicSharedMemorySize, F_SMEM);

    const int n4x = MTOT * DD / 4;
    const int n4w = DD * DD / 4;
    const size_t WSZ = (size_t)DD * DD;

    split_fp32_bf16<<<n4x / 256, 256>>>(x, xhi, xlo, n4x);
    split_fp32_bf16<<<n4w / 256, 256>>>(Wq, whi + 0 * WSZ, wlo + 0 * WSZ, n4w);
    split_fp32_bf16<<<n4w / 256, 256>>>(Wk, whi + 1 * WSZ, wlo + 1 * WSZ, n4w);
    split_fp32_bf16<<<n4w / 256, 256>>>(Wv, whi + 2 * WSZ, wlo + 2 * WSZ, n4w);
    split_fp32_bf16<<<n4w / 256, 256>>>(Wo, whi + 3 * WSZ, wlo + 3 * WSZ, n4w);

    dim3 gg(DD / 128, MTOT / 128);   // (8, 32)
    gemm_mma<<<gg, 256, G_SMEM>>>(xhi, xlo, whi + 0 * WSZ, wlo + 0 * WSZ, bq,
                                  nullptr, qhi, qlo, 1);
    gemm_mma<<<gg, 256, G_SMEM>>>(xhi, xlo, whi + 1 * WSZ, wlo + 1 * WSZ, bk,
                                  nullptr, khi, klo, 1);
    gemm_mma<<<gg, 256, G_SMEM>>>(xhi, xlo, whi + 2 * WSZ, wlo + 2 * WSZ, bv,
                                  nullptr, vhi, vlo, 1);

    dim3 fg(SS / 64, HH, BB);        // (32, 16, 2)
    flash_mma<<<fg, 128, F_SMEM>>>(qhi, qlo, khi, klo, vhi, vlo, ohi, olo);

    gemm_mma<<<gg, 256, G_SMEM>>>(ohi, olo, whi + 3 * WSZ, wlo + 3 * WSZ, bo,
                                  out, nullptr, nullptr, 0);
}

// round 6
// speedup vs baseline: 3.1284x; 1.1571x over previous
#include <cuda_runtime.h>
#include <cuda_bf16.h>
#include <math.h>
#include <stdint.h>

#define BB 2
#define SS 2048
#define DD 1024
#define HH 16
#define DH 64
#define MTOT (BB*SS)   // 4096

// ---------------------------------------------------------------------------
// Scratch (allocation-free rule: __device__ globals)
// ---------------------------------------------------------------------------
__device__ __nv_bfloat16 g_xhi[MTOT*DD], g_xlo[MTOT*DD];
__device__ __nv_bfloat16 g_qhi[MTOT*DD], g_qlo[MTOT*DD];
__device__ __nv_bfloat16 g_khi[MTOT*DD], g_klo[MTOT*DD];
__device__ __nv_bfloat16 g_vhi[MTOT*DD], g_vlo[MTOT*DD];
__device__ __nv_bfloat16 g_ohi[MTOT*DD], g_olo[MTOT*DD];
__device__ __nv_bfloat16 g_whi[4][DD*DD], g_wlo[4][DD*DD];

// ---------------------------------------------------------------------------
// Helpers (baseline ISA only: mma.sync / ldmatrix / cp.async)
// ---------------------------------------------------------------------------
__device__ __forceinline__ uint32_t smem_u32(const void* p) {
    uint32_t r;
    asm("{ .reg .u64 t; cvta.to.shared.u64 t, %1; cvt.u32.u64 %0, t; }"
        : "=r"(r) : "l"(p));
    return r;
}
__device__ __forceinline__ void cp16(uint32_t dst, const void* src) {
    asm volatile("cp.async.cg.shared.global [%0], [%1], 16;" :: "r"(dst), "l"(src));
}
__device__ __forceinline__ void cp_commit() { asm volatile("cp.async.commit_group;"); }
__device__ __forceinline__ void cp_wait0()  { asm volatile("cp.async.wait_group 0;" ::: "memory"); }

__device__ __forceinline__ void ldsm4(uint32_t* r, uint32_t a) {
    asm volatile("ldmatrix.sync.aligned.m8n8.x4.shared.b16 {%0,%1,%2,%3}, [%4];"
                 : "=r"(r[0]), "=r"(r[1]), "=r"(r[2]), "=r"(r[3]) : "r"(a));
}
__device__ __forceinline__ void ldsm4t(uint32_t* r, uint32_t a) {
    asm volatile("ldmatrix.sync.aligned.m8n8.x4.trans.shared.b16 {%0,%1,%2,%3}, [%4];"
                 : "=r"(r[0]), "=r"(r[1]), "=r"(r[2]), "=r"(r[3]) : "r"(a));
}

__device__ __forceinline__ void mma16816(float* d,
    uint32_t a0, uint32_t a1, uint32_t a2, uint32_t a3, uint32_t b0, uint32_t b1) {
    asm volatile(
        "mma.sync.aligned.m16n8k16.row.col.f32.bf16.bf16.f32 "
        "{%0,%1,%2,%3}, {%4,%5,%6,%7}, {%8,%9}, {%0,%1,%2,%3};"
        : "+f"(d[0]), "+f"(d[1]), "+f"(d[2]), "+f"(d[3])
        : "r"(a0), "r"(a1), "r"(a2), "r"(a3), "r"(b0), "r"(b1));
}

__device__ __forceinline__ uint32_t packbf(float lo, float hi) {
    __nv_bfloat162 t = __floats2bfloat162_rn(lo, hi);   // .x = lo half
    return *(uint32_t*)&t;
}
__device__ __forceinline__ float fast_exp2(float x) {
    float y; asm("ex2.approx.ftz.f32 %0, %1;" : "=f"(y) : "f"(x)); return y;
}

// ---------------------------------------------------------------------------
// fp32 -> bf16 (hi, lo) split kernels
// ---------------------------------------------------------------------------
__device__ __forceinline__ void split4(const float* in, __nv_bfloat16* hi,
                                       __nv_bfloat16* lo, int i) {
    float4 v = *(const float4*)(in + (size_t)i * 4);
    __nv_bfloat16 h0 = __float2bfloat16(v.x);
    __nv_bfloat16 h1 = __float2bfloat16(v.y);
    __nv_bfloat16 h2 = __float2bfloat16(v.z);
    __nv_bfloat16 h3 = __float2bfloat16(v.w);
    __nv_bfloat16 l0 = __float2bfloat16(v.x - __bfloat162float(h0));
    __nv_bfloat16 l1 = __float2bfloat16(v.y - __bfloat162float(h1));
    __nv_bfloat16 l2 = __float2bfloat16(v.z - __bfloat162float(h2));
    __nv_bfloat16 l3 = __float2bfloat16(v.w - __bfloat162float(h3));
    __nv_bfloat162* hp = (__nv_bfloat162*)(hi + (size_t)i * 4);
    __nv_bfloat162* lp = (__nv_bfloat162*)(lo + (size_t)i * 4);
    hp[0] = __nv_bfloat162{h0, h1}; hp[1] = __nv_bfloat162{h2, h3};
    lp[0] = __nv_bfloat162{l0, l1}; lp[1] = __nv_bfloat162{l2, l3};
}

__global__ __launch_bounds__(256) void split_fp32_bf16(
    const float* __restrict__ in, __nv_bfloat16* __restrict__ hi,
    __nv_bfloat16* __restrict__ lo, int n4)
{
    int i = blockIdx.x * 256 + threadIdx.x;
    if (i < n4) split4(in, hi, lo, i);
}

// fused split of the 4 weight matrices (grid.y selects the matrix)
__global__ __launch_bounds__(256) void split_weights(
    const float* W0, const float* W1, const float* W2, const float* W3,
    __nv_bfloat16* whi, __nv_bfloat16* wlo)
{
    const float* W = (blockIdx.y == 0 ? W0 : blockIdx.y == 1 ? W1 :
                      blockIdx.y == 2 ? W2 : W3);
    size_t off = (size_t)blockIdx.y * DD * DD;
    int i = blockIdx.x * 256 + threadIdx.x;
    split4(W, whi + off, wlo + off, i);
}

// ---------------------------------------------------------------------------
// mma.sync bf16 3-split GEMM:  C[M,N] = (Ahi+Alo)[M,K] @ (Bhi+Blo)[N,K]^T + bias
// 128x128 tile, BK=32, 256 threads (8 warps 4x2), warp tile 32x64.
// ldmatrix.x4 fragment loads; 80B-padded rows (LDSM conflict-free).
// mode 0: write float C.  mode 1: write split bf16 (Chi, Clo).
// ---------------------------------------------------------------------------
#define G_TILE 10240            // 128 rows * 80B
#define G_STAGE (4*G_TILE)      // Ahi, Alo, Bhi, Blo
#define G_SMEM (2*G_STAGE)      // 81920

__global__ __launch_bounds__(256) void gemm_mma(
    const __nv_bfloat16* __restrict__ Ahi, const __nv_bfloat16* __restrict__ Alo,
    const __nv_bfloat16* __restrict__ Bhi, const __nv_bfloat16* __restrict__ Blo,
    const float* __restrict__ bias,
    float* __restrict__ Cf,
    __nv_bfloat16* __restrict__ Chi, __nv_bfloat16* __restrict__ Clo,
    int mode)
{
    extern __shared__ char smem[];
    const uint32_t sb = smem_u32(smem);
    const int tid = threadIdx.x, lane = tid & 31, wid = tid >> 5;
    const int g = lane >> 2, qr = lane & 3;
    const int mi = lane >> 3, rr = lane & 7;     // ldmatrix lane decomposition
    const int bm = blockIdx.y * 128, bn = blockIdx.x * 128;
    const int wm = (wid >> 1) * 32, wn = (wid & 1) * 64;

    float acc[2][8][4];
    #pragma unroll
    for (int i = 0; i < 2; i++)
        #pragma unroll
        for (int j = 0; j < 8; j++)
            #pragma unroll
            for (int k = 0; k < 4; k++) acc[i][j][k] = 0.0f;

    const int lrow = tid >> 2, lseg = tid & 3;

    auto load_stage = [&](int c) {
        uint32_t base = sb + (uint32_t)(c & 1) * G_STAGE;
        #pragma unroll
        for (int t = 0; t < 4; t++) {
            const __nv_bfloat16* gp = (t == 0 ? Ahi : t == 1 ? Alo : t == 2 ? Bhi : Blo);
            int rb = (t < 2 ? bm : bn);
            #pragma unroll
            for (int h2 = 0; h2 < 2; h2++) {
                int row = h2 * 64 + lrow;
                cp16(base + t * G_TILE + row * 80 + lseg * 16,
                     (const char*)(gp + (size_t)(rb + row) * DD + c * 32) + lseg * 16);
            }
        }
        cp_commit();
    };

    load_stage(0);

    for (int c = 0; c < 32; c++) {
        cp_wait0();
        __syncthreads();
        if (c < 31) load_stage(c + 1);

        uint32_t base = sb + (uint32_t)(c & 1) * G_STAGE;
        #pragma unroll
        for (int kc = 0; kc < 2; kc++) {
            // A fragments: row = wm + mf*16 + (mi&1)*8 + rr, col = kc*32 + (mi>>1)*16
            uint32_t ah[2][4], al[2][4];
            #pragma unroll
            for (int mf = 0; mf < 2; mf++) {
                uint32_t ra = base + (wm + mf * 16 + (mi & 1) * 8 + rr) * 80
                            + kc * 32 + (mi >> 1) * 16;
                ldsm4(ah[mf], ra);
                ldsm4(al[mf], ra + G_TILE);
            }
            // B fragments: one ldsm.x4 covers two nb blocks
            uint32_t bh[8][2], bl[8][2];
            #pragma unroll
            for (int p = 0; p < 4; p++) {
                uint32_t rbq = base + 2 * G_TILE
                             + (wn + (p * 2 + (mi >> 1)) * 8 + rr) * 80
                             + kc * 32 + (mi & 1) * 16;
                uint32_t t4[4];
                ldsm4(t4, rbq);
                bh[p*2][0] = t4[0]; bh[p*2][1] = t4[1];
                bh[p*2+1][0] = t4[2]; bh[p*2+1][1] = t4[3];
                ldsm4(t4, rbq + G_TILE);
                bl[p*2][0] = t4[0]; bl[p*2][1] = t4[1];
                bl[p*2+1][0] = t4[2]; bl[p*2+1][1] = t4[3];
            }
            #pragma unroll
            for (int nb = 0; nb < 8; nb++) {
                #pragma unroll
                for (int mf = 0; mf < 2; mf++) {
                    mma16816(acc[mf][nb], ah[mf][0], ah[mf][1], ah[mf][2], ah[mf][3],
                             bh[nb][0], bh[nb][1]);
                    mma16816(acc[mf][nb], ah[mf][0], ah[mf][1], ah[mf][2], ah[mf][3],
                             bl[nb][0], bl[nb][1]);
                    mma16816(acc[mf][nb], al[mf][0], al[mf][1], al[mf][2], al[mf][3],
                             bh[nb][0], bh[nb][1]);
                }
            }
        }
    }

    // epilogue
    #pragma unroll
    for (int mf = 0; mf < 2; mf++) {
        #pragma unroll
        for (int nb = 0; nb < 8; nb++) {
            int col = bn + wn + nb * 8 + qr * 2;
            float b0 = bias[col], b1 = bias[col + 1];
            int r0 = bm + wm + mf * 16 + g;
            float v00 = acc[mf][nb][0] + b0, v01 = acc[mf][nb][1] + b1;
            float v10 = acc[mf][nb][2] + b0, v11 = acc[mf][nb][3] + b1;
            if (mode == 0) {
                *(float2*)(Cf + (size_t)r0 * DD + col) = make_float2(v00, v01);
                *(float2*)(Cf + (size_t)(r0 + 8) * DD + col) = make_float2(v10, v11);
            } else {
                __nv_bfloat16 h00 = __float2bfloat16(v00), h01 = __float2bfloat16(v01);
                __nv_bfloat16 h10 = __float2bfloat16(v10), h11 = __float2bfloat16(v11);
                __nv_bfloat16 e00 = __float2bfloat16(v00 - __bfloat162float(h00));
                __nv_bfloat16 e01 = __float2bfloat16(v01 - __bfloat162float(h01));
                __nv_bfloat16 e10 = __float2bfloat16(v10 - __bfloat162float(h10));
                __nv_bfloat16 e11 = __float2bfloat16(v11 - __bfloat162float(h11));
                *(__nv_bfloat162*)(Chi + (size_t)r0 * DD + col)       = __nv_bfloat162{h00, h01};
                *(__nv_bfloat162*)(Chi + (size_t)(r0 + 8) * DD + col) = __nv_bfloat162{h10, h11};
                *(__nv_bfloat162*)(Clo + (size_t)r0 * DD + col)       = __nv_bfloat162{e00, e01};
                *(__nv_bfloat162*)(Clo + (size_t)(r0 + 8) * DD + col) = __nv_bfloat162{e10, e11};
            }
        }
    }
}

// ---------------------------------------------------------------------------
// Flash attention on mma.sync bf16 + ldmatrix.
// CTA: 128 threads (4 warps), 64 query rows. Key tiles of 64.
// S = Qhi·Khi + Qhi·Klo + Qlo·Khi (fp32 accum); P split into phi+plo;
// O += phi·Vhi + phi·Vlo + plo·Vhi.
// K,V both cp.async in natural [key][dh] layout (144B padded rows);
// PV B-fragments via ldmatrix.trans. Writes split-bf16 O.
// ---------------------------------------------------------------------------
#define F_TILE 9216             // 64 rows * 144B
#define F_STAGE (4*F_TILE)      // Khi, Klo, Vhi, Vlo
#define F_SMEM (2*F_STAGE)      // 73728
#define EXC 0.18033688011112042f   // 0.125 * log2(e)

__global__ __launch_bounds__(128) void flash_mma(
    const __nv_bfloat16* __restrict__ qhi, const __nv_bfloat16* __restrict__ qlo,
    const __nv_bfloat16* __restrict__ khi, const __nv_bfloat16* __restrict__ klo,
    const __nv_bfloat16* __restrict__ vhi, const __nv_bfloat16* __restrict__ vlo,
    __nv_bfloat16* __restrict__ ohi, __nv_bfloat16* __restrict__ olo)
{
    extern __shared__ char smem[];
    const uint32_t sb = smem_u32(smem);
    const int tid = threadIdx.x, lane = tid & 31, w = tid >> 5;
    const int g = lane >> 2, qr = lane & 3;
    const int mi = lane >> 3, rr = lane & 7;
    const int b = blockIdx.z, h = blockIdx.y;
    const int q0 = blockIdx.x * 64;

    // Q fragments (held in regs for the whole kernel)
    uint32_t qh_[4][4], ql_[4][4];
    {
        const size_t rowb = (size_t)(b * SS + q0 + w * 16 + g) * DD + h * DH;
        #pragma unroll
        for (int kc = 0; kc < 4; kc++) {
            size_t o0 = rowb + kc * 16 + qr * 2;
            qh_[kc][0] = *(const uint32_t*)(qhi + o0);
            qh_[kc][1] = *(const uint32_t*)(qhi + o0 + 8 * DD);
            qh_[kc][2] = *(const uint32_t*)(qhi + o0 + 8);
            qh_[kc][3] = *(const uint32_t*)(qhi + o0 + 8 * DD + 8);
            ql_[kc][0] = *(const uint32_t*)(qlo + o0);
            ql_[kc][1] = *(const uint32_t*)(qlo + o0 + 8 * DD);
            ql_[kc][2] = *(const uint32_t*)(qlo + o0 + 8);
            ql_[kc][3] = *(const uint32_t*)(qlo + o0 + 8 * DD + 8);
        }
    }

    float o_[8][4];
    #pragma unroll
    for (int j = 0; j < 8; j++)
        #pragma unroll
        for (int k = 0; k < 4; k++) o_[j][k] = 0.0f;
    float m0 = -1e30f, m1 = -1e30f, l0 = 0.0f, l1 = 0.0f;

    auto load_tiles = [&](int t) {
        uint32_t base = sb + (uint32_t)(t & 1) * F_STAGE;
        #pragma unroll
        for (int i = 0; i < 16; i++) {
            int flat = i * 128 + tid;           // 0..2047
            int t2 = flat >> 9;                 // tile: khi, klo, vhi, vlo
            int u = flat & 511;
            int row = u >> 3, seg = u & 7;
            const __nv_bfloat16* gp = (t2 == 0 ? khi : t2 == 1 ? klo :
                                       t2 == 2 ? vhi : vlo);
            cp16(base + t2 * F_TILE + row * 144 + seg * 16,
                 (const char*)(gp + (size_t)(b * SS + t * 64 + row) * DD + h * DH)
                 + seg * 16);
        }
        cp_commit();
    };

    load_tiles(0);

    for (int t = 0; t < 32; t++) {
        cp_wait0();
        __syncthreads();
        if (t < 31) load_tiles(t + 1);
        uint32_t base = sb + (uint32_t)(t & 1) * F_STAGE;

        // ---- S = Q K^T (3-split) ----
        float s_[8][4];
        #pragma unroll
        for (int j = 0; j < 8; j++)
            #pragma unroll
            for (int k = 0; k < 4; k++) s_[j][k] = 0.0f;

        #pragma unroll
        for (int kc = 0; kc < 4; kc++) {
            uint32_t kh[8][2], kl[8][2];
            #pragma unroll
            for (int p = 0; p < 4; p++) {
                // rows = keys, col = dh chunk
                uint32_t rk = base + ((p * 2 + (mi >> 1)) * 8 + rr) * 144
                            + kc * 32 + (mi & 1) * 16;
                uint32_t t4[4];
                ldsm4(t4, rk);
                kh[p*2][0] = t4[0]; kh[p*2][1] = t4[1];
                kh[p*2+1][0] = t4[2]; kh[p*2+1][1] = t4[3];
                ldsm4(t4, rk + F_TILE);
                kl[p*2][0] = t4[0]; kl[p*2][1] = t4[1];
                kl[p*2+1][0] = t4[2]; kl[p*2+1][1] = t4[3];
            }
            #pragma unroll
            for (int nb = 0; nb < 8; nb++) {
                mma16816(s_[nb], qh_[kc][0], qh_[kc][1], qh_[kc][2], qh_[kc][3],
                         kh[nb][0], kh[nb][1]);
                mma16816(s_[nb], qh_[kc][0], qh_[kc][1], qh_[kc][2], qh_[kc][3],
                         kl[nb][0], kl[nb][1]);
                mma16816(s_[nb], ql_[kc][0], ql_[kc][1], ql_[kc][2], ql_[kc][3],
                         kh[nb][0], kh[nb][1]);
            }
        }

        // ---- online softmax ----
        float tm0 = -1e30f, tm1 = -1e30f;
        #pragma unroll
        for (int nb = 0; nb < 8; nb++) {
            tm0 = fmaxf(tm0, fmaxf(s_[nb][0], s_[nb][1]));
            tm1 = fmaxf(tm1, fmaxf(s_[nb][2], s_[nb][3]));
        }
        tm0 = fmaxf(tm0, __shfl_xor_sync(0xffffffffu, tm0, 1));
        tm0 = fmaxf(tm0, __shfl_xor_sync(0xffffffffu, tm0, 2));
        tm1 = fmaxf(tm1, __shfl_xor_sync(0xffffffffu, tm1, 1));
        tm1 = fmaxf(tm1, __shfl_xor_sync(0xffffffffu, tm1, 2));

        float mn0 = fmaxf(m0, tm0), mn1 = fmaxf(m1, tm1);
        float sc0 = fast_exp2((m0 - mn0) * EXC), sc1 = fast_exp2((m1 - mn1) * EXC);
        m0 = mn0; m1 = mn1;
        l0 *= sc0; l1 *= sc1;
        #pragma unroll
        for (int nb = 0; nb < 8; nb++) {
            o_[nb][0] *= sc0; o_[nb][1] *= sc0;
            o_[nb][2] *= sc1; o_[nb][3] *= sc1;
        }

        uint32_t ph[8][2], pl[8][2];
        float ps0 = 0.0f, ps1 = 0.0f;
        #pragma unroll
        for (int nb = 0; nb < 8; nb++) {
            float p0 = fast_exp2((s_[nb][0] - m0) * EXC);
            float p1 = fast_exp2((s_[nb][1] - m0) * EXC);
            float p2 = fast_exp2((s_[nb][2] - m1) * EXC);
            float p3 = fast_exp2((s_[nb][3] - m1) * EXC);
            ps0 += p0 + p1; ps1 += p2 + p3;
            __nv_bfloat16 q0b = __float2bfloat16(p0), q1b = __float2bfloat16(p1);
            __nv_bfloat16 q2b = __float2bfloat16(p2), q3b = __float2bfloat16(p3);
            ph[nb][0] = packbf(p0, p1);   // rn-packed hi parts
            ph[nb][1] = packbf(p2, p3);
            // lo parts relative to rn-rounded hi
            __nv_bfloat162 h01 = *(__nv_bfloat162*)&ph[nb][0];
            __nv_bfloat162 h23 = *(__nv_bfloat162*)&ph[nb][1];
            pl[nb][0] = packbf(p0 - __bfloat162float(h01.x),
                               p1 - __bfloat162float(h01.y));
            pl[nb][1] = packbf(p2 - __bfloat162float(h23.x),
                               p3 - __bfloat162float(h23.y));
            (void)q0b; (void)q1b; (void)q2b; (void)q3b;
        }
        ps0 += __shfl_xor_sync(0xffffffffu, ps0, 1);
        ps0 += __shfl_xor_sync(0xffffffffu, ps0, 2);
        ps1 += __shfl_xor_sync(0xffffffffu, ps1, 1);
        ps1 += __shfl_xor_sync(0xffffffffu, ps1, 2);
        l0 += ps0; l1 += ps1;

        // ---- O += P V (phi·Vhi + phi·Vlo + plo·Vhi), V frags via ldsm.trans ----
        #pragma unroll
        for (int kc = 0; kc < 4; kc++) {
            uint32_t a0 = ph[2*kc][0], a1 = ph[2*kc][1];
            uint32_t a2 = ph[2*kc+1][0], a3 = ph[2*kc+1][1];
            uint32_t c0 = pl[2*kc][0], c1 = pl[2*kc][1];
            uint32_t c2 = pl[2*kc+1][0], c3 = pl[2*kc+1][1];
            uint32_t vh[8][2], vl[8][2];
            #pragma unroll
            for (int p = 0; p < 4; p++) {
                // rows = keys kc*16 + (mi&1)*8 + rr ; col = dh block (p*2+(mi>>1))*16
                uint32_t rv = base + 2 * F_TILE
                            + (kc * 16 + (mi & 1) * 8 + rr) * 144
                            + (p * 2 + (mi >> 1)) * 16;
                uint32_t t4[4];
                ldsm4t(t4, rv);
                vh[p*2][0] = t4[0]; vh[p*2][1] = t4[1];
                vh[p*2+1][0] = t4[2]; vh[p*2+1][1] = t4[3];
                ldsm4t(t4, rv + F_TILE);
                vl[p*2][0] = t4[0]; vl[p*2][1] = t4[1];
                vl[p*2+1][0] = t4[2]; vl[p*2+1][1] = t4[3];
            }
            #pragma unroll
            for (int nb = 0; nb < 8; nb++) {
                mma16816(o_[nb], a0, a1, a2, a3, vh[nb][0], vh[nb][1]);
                mma16816(o_[nb], a0, a1, a2, a3, vl[nb][0], vl[nb][1]);
                mma16816(o_[nb], c0, c1, c2, c3, vh[nb][0], vh[nb][1]);
            }
        }
    }

    // ---- epilogue: normalize, split to bf16 hi/lo ----
    float i0 = 1.0f / l0, i1 = 1.0f / l1;
    const size_t rw0 = (size_t)(b * SS + q0 + w * 16 + g) * DD + h * DH;
    #pragma unroll
    for (int nb = 0; nb < 8; nb++) {
        int col = nb * 8 + qr * 2;
        float v00 = o_[nb][0] * i0, v01 = o_[nb][1] * i0;
        float v10 = o_[nb][2] * i1, v11 = o_[nb][3] * i1;
        __nv_bfloat16 h00 = __float2bfloat16(v00), h01 = __float2bfloat16(v01);
        __nv_bfloat16 h10 = __float2bfloat16(v10), h11 = __float2bfloat16(v11);
        __nv_bfloat16 e00 = __float2bfloat16(v00 - __bfloat162float(h00));
        __nv_bfloat16 e01 = __float2bfloat16(v01 - __bfloat162float(h01));
        __nv_bfloat16 e10 = __float2bfloat16(v10 - __bfloat162float(h10));
        __nv_bfloat16 e11 = __float2bfloat16(v11 - __bfloat162float(h11));
        *(__nv_bfloat162*)(ohi + rw0 + col)          = __nv_bfloat162{h00, h01};
        *(__nv_bfloat162*)(ohi + rw0 + 8 * DD + col) = __nv_bfloat162{h10, h11};
        *(__nv_bfloat162*)(olo + rw0 + col)          = __nv_bfloat162{e00, e01};
        *(__nv_bfloat162*)(olo + rw0 + 8 * DD + col) = __nv_bfloat162{e10, e11};
    }
}

// ---------------------------------------------------------------------------
// Launch
// ---------------------------------------------------------------------------
extern "C" void kernel_launch(void* const* d_in, const int* in_sizes, int n_in,
                              void* d_out, int out_size)
{
    const float* x  = (const float*)d_in[0];
    const float* Wq = (const float*)d_in[1];
    const float* bq = (const float*)d_in[2];
    const float* Wk = (const float*)d_in[3];
    const float* bk = (const float*)d_in[4];
    const float* Wv = (const float*)d_in[5];
    const float* bv = (const float*)d_in[6];
    const float* Wo = (const float*)d_in[7];
    const float* bo = (const float*)d_in[8];
    float* out = (float*)d_out;

    __nv_bfloat16 *xhi, *xlo, *qhi, *qlo, *khi, *klo, *vhi, *vlo, *ohi, *olo, *whi, *wlo;
    cudaGetSymbolAddress((void**)&xhi, g_xhi); cudaGetSymbolAddress((void**)&xlo, g_xlo);
    cudaGetSymbolAddress((void**)&qhi, g_qhi); cudaGetSymbolAddress((void**)&qlo, g_qlo);
    cudaGetSymbolAddress((void**)&khi, g_khi); cudaGetSymbolAddress((void**)&klo, g_klo);
    cudaGetSymbolAddress((void**)&vhi, g_vhi); cudaGetSymbolAddress((void**)&vlo, g_vlo);
    cudaGetSymbolAddress((void**)&ohi, g_ohi); cudaGetSymbolAddress((void**)&olo, g_olo);
    cudaGetSymbolAddress((void**)&whi, g_whi); cudaGetSymbolAddress((void**)&wlo, g_wlo);

    cudaFuncSetAttribute(gemm_mma,  cudaFuncAttributeMaxDynamicSharedMemorySize, G_SMEM);
    cudaFuncSetAttribute(flash_mma, cudaFuncAttributeMaxDynamicSharedMemorySize, F_SMEM);

    const int n4x = MTOT * DD / 4;
    const int n4w = DD * DD / 4;
    const size_t WSZ = (size_t)DD * DD;

    split_fp32_bf16<<<n4x / 256, 256>>>(x, xhi, xlo, n4x);
    dim3 wsg(n4w / 256, 4);
    split_weights<<<wsg, 256>>>(Wq, Wk, Wv, Wo, whi, wlo);

    dim3 gg(DD / 128, MTOT / 128);   // (8, 32)
    gemm_mma<<<gg, 256, G_SMEM>>>(xhi, xlo, whi + 0 * WSZ, wlo + 0 * WSZ, bq,
                                  nullptr, qhi, qlo, 1);
    gemm_mma<<<gg, 256, G_SMEM>>>(xhi, xlo, whi + 1 * WSZ, wlo + 1 * WSZ, bk,
                                  nullptr, khi, klo, 1);
    gemm_mma<<<gg, 256, G_SMEM>>>(xhi, xlo, whi + 2 * WSZ, wlo + 2 * WSZ, bv,
                                  nullptr, vhi, vlo, 1);

    dim3 fg(SS / 64, HH, BB);        // (32, 16, 2)
    flash_mma<<<fg, 128, F_SMEM>>>(qhi, qlo, khi, klo, vhi, vlo, ohi, olo);

    gemm_mma<<<gg, 256, G_SMEM>>>(ohi, olo, whi + 3 * WSZ, wlo + 3 * WSZ, bo,
                                  out, nullptr, nullptr, 0);
}